// round 14
// baseline (speedup 1.0000x reference)
#include <cuda_runtime.h>
#include <cuda_bf16.h>
#include <cstdint>

#define E_EDGES   1048576
#define V_SEG     50000
#define V_PAD     50048
#define C_IN      128
#define C_MID     256
#define C_OUT     128
#define KTOT      384      // 3 x 128 split-K (hi*whi + lo*whi + hi*wlo)
#define NCHUNK    6        // KTOT / 64
#define NCHUNK2   12       // gemm2: 3 x 256 / 64

// ---------------- device scratch ----------------
__device__ __align__(16) __nv_bfloat16 g_xhi[(size_t)E_EDGES * C_IN];   // sorted order
__device__ __align__(16) __nv_bfloat16 g_xlo[(size_t)E_EDGES * C_IN];   // sorted order
__device__ __align__(16) __nv_bfloat16 g_B1[C_MID * KTOT];   // [256][384] = [Whi|Whi|Wlo]
__device__ __align__(16) __nv_bfloat16 g_B3[C_OUT * KTOT];   // [128][384]
__device__ __align__(16) __nv_bfloat16 g_B2v[C_OUT * 3 * C_MID]; // [128][768]
__device__ __align__(16) __nv_bfloat16 g_zhi[(size_t)V_PAD * C_MID];
__device__ __align__(16) __nv_bfloat16 g_zlo[(size_t)V_PAD * C_MID];
__device__ float g_zvmax[V_PAD * C_MID];
__device__ float g_zvertex[V_SEG * C_OUT];
// counting sort
__device__ unsigned g_count[V_PAD];
__device__ unsigned g_offset[V_PAD];
__device__ unsigned g_bsum[256];
__device__ unsigned g_btop[256];
__device__ int g_order[E_EDGES];   // sorted pos -> original edge
__device__ int g_svid[E_EDGES];    // vid in sorted order (non-decreasing)

// ---------------- helpers ----------------
__device__ __forceinline__ uint32_t smem_to_u32(const void* p) {
    uint32_t a;
    asm("{ .reg .u64 t; cvta.to.shared.u64 t, %1; cvt.u32.u64 %0, t; }" : "=r"(a) : "l"(p));
    return a;
}
#define SWZ(o) ((o) ^ (((o) >> 3) & 0x70))

#define CP_ASYNC16(dst, src) \
    asm volatile("cp.async.cg.shared.global [%0], [%1], 16;" :: "r"(dst), "l"(src))
#define CP_COMMIT() asm volatile("cp.async.commit_group;" ::: "memory")
#define CP_WAIT1()  asm volatile("cp.async.wait_group 1;" ::: "memory")
#define CP_WAIT0()  asm volatile("cp.async.wait_group 0;" ::: "memory")

#define LDSM_X4(r0, r1, r2, r3, addr) \
    asm volatile("ldmatrix.sync.aligned.m8n8.x4.shared.b16 {%0,%1,%2,%3}, [%4];" \
                 : "=r"(r0), "=r"(r1), "=r"(r2), "=r"(r3) : "r"(addr))

#define MMA16816(d, a, b) \
    asm volatile("mma.sync.aligned.m16n8k16.row.col.f32.bf16.bf16.f32 " \
                 "{%0,%1,%2,%3}, {%4,%5,%6,%7}, {%8,%9}, {%0,%1,%2,%3};" \
                 : "+f"((d)[0]), "+f"((d)[1]), "+f"((d)[2]), "+f"((d)[3]) \
                 : "r"((a)[0]), "r"((a)[1]), "r"((a)[2]), "r"((a)[3]), \
                   "r"((b)[0]), "r"((b)[1]))

__device__ __forceinline__ void atomicMaxFloat(float* addr, float value) {
    if (value >= 0.0f) atomicMax(reinterpret_cast<int*>(addr), __float_as_int(value));
    else               atomicMin(reinterpret_cast<unsigned int*>(addr), __float_as_uint(value));
}

// ---------------- mma pieces ----------------
// load one 128-row x 128-byte tile, 256-thread cooperative
__device__ __forceinline__ void load_tile(uint32_t sdst, const char* base, int stride, int tid) {
#pragma unroll
    for (int i = 0; i < 4; i++) {
        int idx = i * 256 + tid;
        int row = idx >> 3, col = (idx & 7) << 4;
        CP_ASYNC16(sdst + SWZ(row * 128 + col), base + (size_t)row * stride + col);
    }
}

// 512-thread cooperative variant
__device__ __forceinline__ void load_tile512(uint32_t sdst, const char* base, int stride, int tid) {
#pragma unroll
    for (int i = 0; i < 2; i++) {
        int idx = i * 512 + tid;
        int row = idx >> 3, col = (idx & 7) << 4;
        CP_ASYNC16(sdst + SWZ(row * 128 + col), base + (size_t)row * stride + col);
    }
}

__device__ __forceinline__ void compute_stage(uint32_t sA, uint32_t sB,
                                              float acc[2][8][4],
                                              int lane, int warp_m, int warp_n) {
    const int g = lane >> 3, lr = lane & 7;
#pragma unroll
    for (int ks = 0; ks < 4; ks++) {
        uint32_t a[2][4];
#pragma unroll
        for (int mi = 0; mi < 2; mi++) {
            int row = warp_m * 32 + mi * 16 + lr + ((g & 1) << 3);
            int kb  = ks * 32 + ((g >> 1) << 4);
            LDSM_X4(a[mi][0], a[mi][1], a[mi][2], a[mi][3], sA + SWZ(row * 128 + kb));
        }
        uint32_t b[8][2];
#pragma unroll
        for (int nj2 = 0; nj2 < 4; nj2++) {
            int nrow = warp_n * 64 + nj2 * 16 + lr + ((g >> 1) << 3);
            int kb   = ks * 32 + ((g & 1) << 4);
            uint32_t r0, r1, r2, r3;
            LDSM_X4(r0, r1, r2, r3, sB + SWZ(nrow * 128 + kb));
            b[nj2 * 2][0] = r0;     b[nj2 * 2][1] = r1;
            b[nj2 * 2 + 1][0] = r2; b[nj2 * 2 + 1][1] = r3;
        }
#pragma unroll
        for (int mi = 0; mi < 2; mi++)
#pragma unroll
            for (int nj = 0; nj < 8; nj++)
                MMA16816(acc[mi][nj], a[mi], b[nj]);
    }
}

// A resident (4x16KB) once; B 3-stage pipelined, ONE barrier per chunk (R8-proven, 256 thr).
__device__ __forceinline__ void mma_mainloop(const __nv_bfloat16* __restrict__ Bmat,
                                             int arow0, int bcol0,
                                             uint32_t sbase, float acc[2][8][4],
                                             int tid, int lane, int warp_m, int warp_n) {
    const uint32_t sB[3] = {sbase + 65536, sbase + 81920, sbase + 98304};
    const char* xh = (const char*)g_xhi + (size_t)arow0 * 256;
    const char* xl = (const char*)g_xlo + (size_t)arow0 * 256;
    const char* bb = (const char*)Bmat + (size_t)bcol0 * (KTOT * 2);

    const char* asrc[4] = {xh, xh + 128, xl, xl + 128};
#pragma unroll
    for (int t = 0; t < 4; t++)
        load_tile(sbase + t * 16384, asrc[t], 256, tid);
    load_tile(sB[0], bb, 768, tid);
    CP_COMMIT();
    load_tile(sB[1], bb + 128, 768, tid);
    CP_COMMIT();

    const uint32_t sAoff[NCHUNK] = {0, 16384, 32768, 49152, 0, 16384};
#pragma unroll
    for (int c = 0; c < NCHUNK; c++) {
        if (c < NCHUNK - 1) CP_WAIT1(); else CP_WAIT0();
        __syncthreads();
        if (c + 2 < NCHUNK) {
            load_tile(sB[(c + 2) % 3], bb + (c + 2) * 128, 768, tid);
            CP_COMMIT();
        }
        compute_stage(sbase + sAoff[c], sB[c % 3], acc, lane, warp_m, warp_n);
    }
    __syncthreads();   // epilogue reuses smem
}

// ---------------- counting sort ----------------
__global__ void k_init(int n4) {
    int i = blockIdx.x * blockDim.x + threadIdx.x;
    if (i < V_PAD) g_count[i] = 0;
    const float NEG_INF = __int_as_float(0xFF800000);
    if (i < n4)
        reinterpret_cast<float4*>(g_zvmax)[i] = make_float4(NEG_INF, NEG_INF, NEG_INF, NEG_INF);
}

__global__ void k_hist(const int* __restrict__ vid) {
    int e4 = blockIdx.x * 256 + threadIdx.x;
    int4 v = __ldg(reinterpret_cast<const int4*>(vid) + e4);
    atomicAdd(&g_count[v.x], 1u);
    atomicAdd(&g_count[v.y], 1u);
    atomicAdd(&g_count[v.z], 1u);
    atomicAdd(&g_count[v.w], 1u);
}

__global__ void k_scan_part() {
    __shared__ unsigned s[256];
    int b = blockIdx.x, t = threadIdx.x, i = b * 256 + t;
    s[t] = (i < V_PAD) ? g_count[i] : 0u;
    __syncthreads();
    for (int o = 128; o > 0; o >>= 1) {
        if (t < o) s[t] += s[t + o];
        __syncthreads();
    }
    if (t == 0) g_bsum[b] = s[0];
}

__global__ void k_scan_top() {
    __shared__ unsigned s[256];
    int t = threadIdx.x;
    unsigned v = (t < 196) ? g_bsum[t] : 0u;
    s[t] = v;
    __syncthreads();
    for (int o = 1; o < 256; o <<= 1) {
        unsigned u = (t >= o) ? s[t - o] : 0u;
        __syncthreads();
        s[t] += u;
        __syncthreads();
    }
    g_btop[t] = s[t] - v;
}

__global__ void k_scan_out() {
    __shared__ unsigned s[256];
    int b = blockIdx.x, t = threadIdx.x, i = b * 256 + t;
    unsigned c = (i < V_PAD) ? g_count[i] : 0u;
    s[t] = c;
    __syncthreads();
    for (int o = 1; o < 256; o <<= 1) {
        unsigned u = (t >= o) ? s[t - o] : 0u;
        __syncthreads();
        s[t] += u;
        __syncthreads();
    }
    if (i < V_PAD) g_offset[i] = g_btop[b] + s[t] - c;
}

__global__ void k_scatter(const int* __restrict__ vid) {
    int e = blockIdx.x * 256 + threadIdx.x;
    int v = __ldg(&vid[e]);
    unsigned p = atomicAdd(&g_offset[v], 1u);
    g_order[p] = e;
    g_svid[p] = v;
}

// ---------------- prep ----------------
__global__ void k_prep_w(const float* __restrict__ W1,
                         const float* __restrict__ W2e,
                         const float* __restrict__ W2v) {
    int i = blockIdx.x * 256 + threadIdx.x;
    if (i < C_MID * C_IN) {
        int n = i >> 7, k = i & 127;
        float w = W1[i];
        __nv_bfloat16 hi = __float2bfloat16(w);
        __nv_bfloat16 lo = __float2bfloat16(w - __bfloat162float(hi));
        g_B1[n * KTOT + k] = hi;
        g_B1[n * KTOT + 128 + k] = hi;
        g_B1[n * KTOT + 256 + k] = lo;
    }
    if (i < C_OUT * C_IN) {
        int n = i >> 7, k = i & 127;
        float w = W2e[i];
        __nv_bfloat16 hi = __float2bfloat16(w);
        __nv_bfloat16 lo = __float2bfloat16(w - __bfloat162float(hi));
        g_B3[n * KTOT + k] = hi;
        g_B3[n * KTOT + 128 + k] = hi;
        g_B3[n * KTOT + 256 + k] = lo;
    }
    if (i < C_OUT * C_MID) {
        int n = i >> 8, k = i & 255;
        float w = W2v[i];
        __nv_bfloat16 hi = __float2bfloat16(w);
        __nv_bfloat16 lo = __float2bfloat16(w - __bfloat162float(hi));
        g_B2v[n * 768 + k] = hi;
        g_B2v[n * 768 + 256 + k] = hi;
        g_B2v[n * 768 + 512 + k] = lo;
    }
}

// gather-split: sorted row p <- original edge order[p]
__global__ void k_split_x(const float* __restrict__ x) {
    size_t i = (size_t)blockIdx.x * 256 + threadIdx.x;   // unit = 4 floats
    int prow = (int)(i >> 5);
    int q = (int)(i & 31);
    int e = __ldg(&g_order[prow]);
    float4 v = __ldg(reinterpret_cast<const float4*>(x + (size_t)e * C_IN) + q);
    ushort4 h, l;
    __nv_bfloat16 hb, lb;
    hb = __float2bfloat16(v.x); lb = __float2bfloat16(v.x - __bfloat162float(hb));
    h.x = *(unsigned short*)&hb; l.x = *(unsigned short*)&lb;
    hb = __float2bfloat16(v.y); lb = __float2bfloat16(v.y - __bfloat162float(hb));
    h.y = *(unsigned short*)&hb; l.y = *(unsigned short*)&lb;
    hb = __float2bfloat16(v.z); lb = __float2bfloat16(v.z - __bfloat162float(hb));
    h.z = *(unsigned short*)&hb; l.z = *(unsigned short*)&lb;
    hb = __float2bfloat16(v.w); lb = __float2bfloat16(v.w - __bfloat162float(hb));
    h.w = *(unsigned short*)&hb; l.w = *(unsigned short*)&lb;
    reinterpret_cast<ushort4*>(g_xhi)[i] = h;
    reinterpret_cast<ushort4*>(g_xlo)[i] = l;
}

// fix -inf -> 0, add deferred b1, split z_vmax to bf16 hi/lo
__global__ void k_split_z(const float* __restrict__ b1) {
    size_t i = (size_t)blockIdx.x * 256 + threadIdx.x;
    if (i >= (size_t)V_PAD * C_MID / 4) return;
    float4 v = reinterpret_cast<const float4*>(g_zvmax)[i];
    float4 bb = __ldg(reinterpret_cast<const float4*>(b1) + (i & 63));
    v.x = (v.x < -1e38f) ? 0.0f : v.x + bb.x;
    v.y = (v.y < -1e38f) ? 0.0f : v.y + bb.y;
    v.z = (v.z < -1e38f) ? 0.0f : v.z + bb.z;
    v.w = (v.w < -1e38f) ? 0.0f : v.w + bb.w;
    ushort4 h, l;
    __nv_bfloat16 hb, lb;
    hb = __float2bfloat16(v.x); lb = __float2bfloat16(v.x - __bfloat162float(hb));
    h.x = *(unsigned short*)&hb; l.x = *(unsigned short*)&lb;
    hb = __float2bfloat16(v.y); lb = __float2bfloat16(v.y - __bfloat162float(hb));
    h.y = *(unsigned short*)&hb; l.y = *(unsigned short*)&lb;
    hb = __float2bfloat16(v.z); lb = __float2bfloat16(v.z - __bfloat162float(hb));
    h.z = *(unsigned short*)&hb; l.z = *(unsigned short*)&lb;
    hb = __float2bfloat16(v.w); lb = __float2bfloat16(v.w - __bfloat162float(hb));
    h.w = *(unsigned short*)&hb; l.w = *(unsigned short*)&lb;
    reinterpret_cast<uint2*>(g_zhi)[i] = make_uint2((unsigned)h.x | ((unsigned)h.y << 16),
                                                    (unsigned)h.z | ((unsigned)h.w << 16));
    reinterpret_cast<uint2*>(g_zlo)[i] = make_uint2((unsigned)l.x | ((unsigned)l.y << 16),
                                                    (unsigned)l.z | ((unsigned)l.w << 16));
}

// ---------------- GEMM1: 512 threads, full N=256 per CTA, A loaded once ----------------
// smem: [0,64K) A tiles; [64K,160K) 3 x 32KB B superchunks (half0|half1 16KB each).
// Epilogue reuses [0,133K) as 128x260 fp32 scratch.
__global__ void __launch_bounds__(512, 1)
k_mma1() {
    extern __shared__ char smem[];
    uint32_t sbase = smem_to_u32(smem);
    __shared__ int s_vid[128];
    const int tid = threadIdx.x, wid = tid >> 5, lane = tid & 31;
    const int warp_m = wid & 3, warp_n = wid >> 2;   // warp_n in 0..3 -> N cols warp_n*64
    const int half = warp_n >> 1, wn_loc = warp_n & 1;
    const int arow0 = blockIdx.x * 128;

    if (tid < 128) s_vid[tid] = __ldg(&g_svid[arow0 + tid]);

    const uint32_t sB[3] = {sbase + 65536, sbase + 98304, sbase + 131072};
    const char* xh = (const char*)g_xhi + (size_t)arow0 * 256;
    const char* xl = (const char*)g_xlo + (size_t)arow0 * 256;
    const char* bb0 = (const char*)g_B1;                        // half0: N rows [0,128)
    const char* bb1 = (const char*)g_B1 + (size_t)128 * 768;    // half1: N rows [128,256)
    const char* asrc[4] = {xh, xh + 128, xl, xl + 128};
    const uint32_t sAoff[NCHUNK] = {0, 16384, 32768, 49152, 0, 16384};

    // A (64 KB) + superchunk 0 in group0; superchunk 1 in group1
#pragma unroll
    for (int t = 0; t < 4; t++)
        load_tile512(sbase + t * 16384, asrc[t], 256, tid);
    load_tile512(sB[0], bb0, 768, tid);
    load_tile512(sB[0] + 16384, bb1, 768, tid);
    CP_COMMIT();
    load_tile512(sB[1], bb0 + 128, 768, tid);
    load_tile512(sB[1] + 16384, bb1 + 128, 768, tid);
    CP_COMMIT();

    float acc[2][8][4] = {};
#pragma unroll
    for (int c = 0; c < NCHUNK; c++) {
        if (c < NCHUNK - 1) CP_WAIT1(); else CP_WAIT0();
        __syncthreads();
        if (c + 2 < NCHUNK) {
            load_tile512(sB[(c + 2) % 3], bb0 + (c + 2) * 128, 768, tid);
            load_tile512(sB[(c + 2) % 3] + 16384, bb1 + (c + 2) * 128, 768, tid);
            CP_COMMIT();
        }
        compute_stage(sbase + sAoff[c], sB[c % 3] + half * 16384, acc, lane, warp_m, wn_loc);
    }
    __syncthreads();

    // dump fragments to smem [128 rows][stride 260]
    float* s_acc = reinterpret_cast<float*>(smem);
    const int lr4 = lane >> 2, lc2 = (lane & 3) * 2;
#pragma unroll
    for (int mi = 0; mi < 2; mi++) {
        int r0 = warp_m * 32 + mi * 16 + lr4;
#pragma unroll
        for (int nj = 0; nj < 8; nj++) {
            int col = warp_n * 64 + nj * 8 + lc2;
            s_acc[r0 * 260 + col]           = acc[mi][nj][0];
            s_acc[r0 * 260 + col + 1]       = acc[mi][nj][1];
            s_acc[(r0 + 8) * 260 + col]     = acc[mi][nj][2];
            s_acc[(r0 + 8) * 260 + col + 1] = acc[mi][nj][3];
        }
    }
    __syncthreads();

    // per-column run-max over sorted rows: ~1 atomic per (vertex run, col)
    const int col = tid & 255;
    const int rbeg = (tid >> 8) * 64;
    int vcur = s_vid[rbeg];
    float cur = s_acc[rbeg * 260 + col];
    for (int r = rbeg + 1; r < rbeg + 64; r++) {
        int v = s_vid[r];
        float val = s_acc[r * 260 + col];
        if (v != vcur) {
            atomicMaxFloat(&g_zvmax[(size_t)vcur * C_MID + col], cur);
            vcur = v;
            cur = val;
        } else {
            cur = fmaxf(cur, val);
        }
    }
    atomicMaxFloat(&g_zvmax[(size_t)vcur * C_MID + col], cur);
}

// ---------------- GEMM2 (HMMA): z_vertex = split(z_vmax+b1) @ W2v^T (R8-proven) ----------------
__global__ void __launch_bounds__(256, 2)
k_mma2() {
    extern __shared__ char smem[];
    uint32_t sbase = smem_to_u32(smem);
    const int tid = threadIdx.x, wid = tid >> 5, lane = tid & 31;
    const int warp_m = wid & 3, warp_n = wid >> 2;
    const int arow0 = blockIdx.x * 128;

    const uint32_t sA[2] = {sbase, sbase + 16384};
    const uint32_t sB[2] = {sbase + 32768, sbase + 49152};
    const char* zh = (const char*)g_zhi + (size_t)arow0 * 512;
    const char* zl = (const char*)g_zlo + (size_t)arow0 * 512;
    const char* bb = (const char*)g_B2v;

    float acc[2][8][4] = {};
    load_tile(sA[0], zh, 512, tid);
    load_tile(sB[0], bb, 1536, tid);
    CP_COMMIT();
#pragma unroll
    for (int c = 0; c < NCHUNK2; c++) {
        if (c < NCHUNK2 - 1) {
            int n = c + 1;
            const char* ab = ((n < 4 || n >= 8) ? zh : zl) + (n & 3) * 128;
            load_tile(sA[n & 1], ab, 512, tid);
            load_tile(sB[n & 1], bb + n * 128, 1536, tid);
            CP_COMMIT();
            CP_WAIT1();
        } else {
            CP_WAIT0();
        }
        __syncthreads();
        compute_stage(sA[c & 1], sB[c & 1], acc, lane, warp_m, warp_n);
        __syncthreads();
    }

    const int lr4 = lane >> 2, lc2 = (lane & 3) * 2;
#pragma unroll
    for (int mi = 0; mi < 2; mi++) {
        int p0 = arow0 + warp_m * 32 + mi * 16 + lr4;
        int p1 = p0 + 8;
#pragma unroll
        for (int nj = 0; nj < 8; nj++) {
            int col = warp_n * 64 + nj * 8 + lc2;
            if (p0 < V_SEG)
                *reinterpret_cast<float2*>(&g_zvertex[(size_t)p0 * C_OUT + col]) =
                    make_float2(acc[mi][nj][0], acc[mi][nj][1]);
            if (p1 < V_SEG)
                *reinterpret_cast<float2*>(&g_zvertex[(size_t)p1 * C_OUT + col]) =
                    make_float2(acc[mi][nj][2], acc[mi][nj][3]);
        }
    }
}

// ---------------- GEMM3: out[order[p]] = xs@W2e^T + z_vertex[svid[p]] (R8-proven) ----------------
__global__ void __launch_bounds__(256, 2)
k_mma3(float* __restrict__ out) {
    extern __shared__ char smem[];
    uint32_t sbase = smem_to_u32(smem);
    const int tid = threadIdx.x, wid = tid >> 5, lane = tid & 31;
    const int warp_m = wid & 3, warp_n = wid >> 2;
    const int arow0 = blockIdx.x * 128;

    float acc[2][8][4] = {};
    mma_mainloop(g_B3, arow0, 0, sbase, acc, tid, lane, warp_m, warp_n);

    const int lr4 = lane >> 2, lc2 = (lane & 3) * 2;
#pragma unroll
    for (int mi = 0; mi < 2; mi++) {
        int p0 = arow0 + warp_m * 32 + mi * 16 + lr4;
        int p1 = p0 + 8;
        int v0 = __ldg(&g_svid[p0]);
        int v1 = __ldg(&g_svid[p1]);
        int e0 = __ldg(&g_order[p0]);
        int e1 = __ldg(&g_order[p1]);
        const float* z0 = g_zvertex + (size_t)v0 * C_OUT + warp_n * 64 + lc2;
        const float* z1 = g_zvertex + (size_t)v1 * C_OUT + warp_n * 64 + lc2;
        float* o0 = out + (size_t)e0 * C_OUT + warp_n * 64 + lc2;
        float* o1 = out + (size_t)e1 * C_OUT + warp_n * 64 + lc2;
#pragma unroll
        for (int nj = 0; nj < 8; nj++) {
            float2 za = __ldg(reinterpret_cast<const float2*>(z0 + nj * 8));
            float2 zb = __ldg(reinterpret_cast<const float2*>(z1 + nj * 8));
            *reinterpret_cast<float2*>(o0 + nj * 8) =
                make_float2(acc[mi][nj][0] + za.x, acc[mi][nj][1] + za.y);
            *reinterpret_cast<float2*>(o1 + nj * 8) =
                make_float2(acc[mi][nj][2] + zb.x, acc[mi][nj][3] + zb.y);
        }
    }
}

// ---------------- launch ----------------
static constexpr int SMEM_MMA1 = 65536 + 3 * 32768;   // 160 KB: A 64KB + B 3x32KB superchunks
static constexpr int SMEM_MMA  = 65536 + 3 * 16384;   // 112 KB
static constexpr int SMEM_MMA2 = 65536;

extern "C" void kernel_launch(void* const* d_in, const int* in_sizes, int n_in,
                              void* d_out, int out_size) {
    const float* x   = (const float*)d_in[0];
    const int*   vid = (const int*)d_in[1];
    const float* W1  = (const float*)d_in[2];
    const float* b1  = (const float*)d_in[3];
    const float* W2e = (const float*)d_in[4];
    const float* W2v = (const float*)d_in[5];
    float* out = (float*)d_out;

    cudaFuncSetAttribute(k_mma1, cudaFuncAttributeMaxDynamicSharedMemorySize, SMEM_MMA1);
    cudaFuncSetAttribute(k_mma2, cudaFuncAttributeMaxDynamicSharedMemorySize, SMEM_MMA2);
    cudaFuncSetAttribute(k_mma3, cudaFuncAttributeMaxDynamicSharedMemorySize, SMEM_MMA);

    const int N4 = V_PAD * C_MID / 4;
    k_prep_w<<<128, 256>>>(W1, W2e, W2v);
    k_init<<<(N4 + 255) / 256, 256>>>(N4);
    k_hist<<<E_EDGES / 1024, 256>>>(vid);
    k_scan_part<<<196, 256>>>();
    k_scan_top<<<1, 256>>>();
    k_scan_out<<<196, 256>>>();
    k_scatter<<<E_EDGES / 256, 256>>>(vid);
    k_split_x<<<(E_EDGES * C_IN / 4) / 256, 256>>>(x);
    k_mma1<<<E_EDGES / 128, 512, SMEM_MMA1>>>();
    k_split_z<<<(V_PAD * C_MID / 4 + 255) / 256, 256>>>(b1);
    k_mma2<<<V_PAD / 128, 256, SMEM_MMA2>>>();
    k_mma3<<<E_EDGES / 128, 256, SMEM_MMA>>>(out);
}

// round 15
// speedup vs baseline: 1.1097x; 1.1097x over previous
#include <cuda_runtime.h>
#include <cuda_bf16.h>
#include <cstdint>

#define E_EDGES   1048576
#define V_SEG     50000
#define V_PAD     50048
#define C_IN      128
#define C_MID     256
#define C_OUT     128
#define KTOT      384      // 3 x 128 split-K (hi*whi + lo*whi + hi*wlo)
#define NCHUNK    6        // KTOT / 64
#define NCHUNK2   12       // gemm2: 3 x 256 / 64

// ---------------- device scratch ----------------
__device__ __align__(16) __nv_bfloat16 g_xhi[(size_t)E_EDGES * C_IN];   // sorted order
__device__ __align__(16) __nv_bfloat16 g_xlo[(size_t)E_EDGES * C_IN];   // sorted order
__device__ __align__(16) __nv_bfloat16 g_B1[C_MID * KTOT];   // [256][384] = [Whi|Whi|Wlo]
__device__ __align__(16) __nv_bfloat16 g_B3[C_OUT * KTOT];   // [128][384]
__device__ __align__(16) __nv_bfloat16 g_B2v[C_OUT * 3 * C_MID]; // [128][768]
__device__ __align__(16) __nv_bfloat16 g_zhi[(size_t)V_PAD * C_MID];
__device__ __align__(16) __nv_bfloat16 g_zlo[(size_t)V_PAD * C_MID];
__device__ float g_zvmax[V_PAD * C_MID];
__device__ float g_zvertex[V_SEG * C_OUT];
// counting sort
__device__ unsigned g_count[V_PAD];
__device__ unsigned g_offset[V_PAD];
__device__ unsigned g_bsum[256];
__device__ unsigned g_btop[256];
__device__ int g_order[E_EDGES];   // sorted pos -> original edge
__device__ int g_svid[E_EDGES];    // vid in sorted order (non-decreasing)

// ---------------- helpers ----------------
__device__ __forceinline__ uint32_t smem_to_u32(const void* p) {
    uint32_t a;
    asm("{ .reg .u64 t; cvta.to.shared.u64 t, %1; cvt.u32.u64 %0, t; }" : "=r"(a) : "l"(p));
    return a;
}
#define SWZ(o) ((o) ^ (((o) >> 3) & 0x70))

#define CP_ASYNC16(dst, src) \
    asm volatile("cp.async.cg.shared.global [%0], [%1], 16;" :: "r"(dst), "l"(src))
#define CP_COMMIT() asm volatile("cp.async.commit_group;" ::: "memory")
#define CP_WAIT1()  asm volatile("cp.async.wait_group 1;" ::: "memory")
#define CP_WAIT0()  asm volatile("cp.async.wait_group 0;" ::: "memory")

#define LDSM_X4(r0, r1, r2, r3, addr) \
    asm volatile("ldmatrix.sync.aligned.m8n8.x4.shared.b16 {%0,%1,%2,%3}, [%4];" \
                 : "=r"(r0), "=r"(r1), "=r"(r2), "=r"(r3) : "r"(addr))

#define MMA16816(d, a, b) \
    asm volatile("mma.sync.aligned.m16n8k16.row.col.f32.bf16.bf16.f32 " \
                 "{%0,%1,%2,%3}, {%4,%5,%6,%7}, {%8,%9}, {%0,%1,%2,%3};" \
                 : "+f"((d)[0]), "+f"((d)[1]), "+f"((d)[2]), "+f"((d)[3]) \
                 : "r"((a)[0]), "r"((a)[1]), "r"((a)[2]), "r"((a)[3]), \
                   "r"((b)[0]), "r"((b)[1]))

__device__ __forceinline__ void atomicMaxFloat(float* addr, float value) {
    if (value >= 0.0f) atomicMax(reinterpret_cast<int*>(addr), __float_as_int(value));
    else               atomicMin(reinterpret_cast<unsigned int*>(addr), __float_as_uint(value));
}

// ---------------- mma pieces ----------------
// load one 128-row x 128-byte tile, gmem row stride = stride bytes
__device__ __forceinline__ void load_tile(uint32_t sdst, const char* base, int stride, int tid) {
#pragma unroll
    for (int i = 0; i < 4; i++) {
        int idx = i * 256 + tid;
        int row = idx >> 3, col = (idx & 7) << 4;
        CP_ASYNC16(sdst + SWZ(row * 128 + col), base + (size_t)row * stride + col);
    }
}

__device__ __forceinline__ void compute_stage(uint32_t sA, uint32_t sB,
                                              float acc[2][8][4],
                                              int lane, int warp_m, int warp_n) {
    const int g = lane >> 3, lr = lane & 7;
#pragma unroll
    for (int ks = 0; ks < 4; ks++) {
        uint32_t a[2][4];
#pragma unroll
        for (int mi = 0; mi < 2; mi++) {
            int row = warp_m * 32 + mi * 16 + lr + ((g & 1) << 3);
            int kb  = ks * 32 + ((g >> 1) << 4);
            LDSM_X4(a[mi][0], a[mi][1], a[mi][2], a[mi][3], sA + SWZ(row * 128 + kb));
        }
        uint32_t b[8][2];
#pragma unroll
        for (int nj2 = 0; nj2 < 4; nj2++) {
            int nrow = warp_n * 64 + nj2 * 16 + lr + ((g >> 1) << 3);
            int kb   = ks * 32 + ((g & 1) << 4);
            uint32_t r0, r1, r2, r3;
            LDSM_X4(r0, r1, r2, r3, sB + SWZ(nrow * 128 + kb));
            b[nj2 * 2][0] = r0;     b[nj2 * 2][1] = r1;
            b[nj2 * 2 + 1][0] = r2; b[nj2 * 2 + 1][1] = r3;
        }
#pragma unroll
        for (int mi = 0; mi < 2; mi++)
#pragma unroll
            for (int nj = 0; nj < 8; nj++)
                MMA16816(acc[mi][nj], a[mi], b[nj]);
    }
}

// A resident in smem (4x16KB: hi k0, hi k1, lo k0, lo k1) loaded ONCE;
// B 3-stage pipelined, ONE barrier per chunk. smem 112 KB.
__device__ __forceinline__ void mma_mainloop(const __nv_bfloat16* __restrict__ Bmat,
                                             int arow0, int bcol0,
                                             uint32_t sbase, float acc[2][8][4],
                                             int tid, int lane, int warp_m, int warp_n) {
    const uint32_t sB[3] = {sbase + 65536, sbase + 81920, sbase + 98304};
    const char* xh = (const char*)g_xhi + (size_t)arow0 * 256;
    const char* xl = (const char*)g_xlo + (size_t)arow0 * 256;
    const char* bb = (const char*)Bmat + (size_t)bcol0 * (KTOT * 2);

    // group 0: all of A (64 KB) + B chunk 0 ; group 1: B chunk 1
    const char* asrc[4] = {xh, xh + 128, xl, xl + 128};
#pragma unroll
    for (int t = 0; t < 4; t++)
        load_tile(sbase + t * 16384, asrc[t], 256, tid);
    load_tile(sB[0], bb, 768, tid);
    CP_COMMIT();
    load_tile(sB[1], bb + 128, 768, tid);
    CP_COMMIT();

    const uint32_t sAoff[NCHUNK] = {0, 16384, 32768, 49152, 0, 16384};
#pragma unroll
    for (int c = 0; c < NCHUNK; c++) {
        if (c < NCHUNK - 1) CP_WAIT1(); else CP_WAIT0();
        __syncthreads();
        if (c + 2 < NCHUNK) {
            load_tile(sB[(c + 2) % 3], bb + (c + 2) * 128, 768, tid);
            CP_COMMIT();
        }
        compute_stage(sbase + sAoff[c], sB[c % 3], acc, lane, warp_m, warp_n);
    }
    __syncthreads();   // epilogue reuses smem
}

// ---------------- counting sort ----------------
__global__ void k_zero_count() {
    int i = blockIdx.x * 256 + threadIdx.x;
    if (i < V_PAD) g_count[i] = 0;
}

__global__ void k_hist(const int* __restrict__ vid) {
    int e = blockIdx.x * 256 + threadIdx.x;
    atomicAdd(&g_count[__ldg(&vid[e])], 1u);
}

__global__ void k_scan_part() {
    __shared__ unsigned s[256];
    int b = blockIdx.x, t = threadIdx.x, i = b * 256 + t;
    s[t] = (i < V_PAD) ? g_count[i] : 0u;
    __syncthreads();
    for (int o = 128; o > 0; o >>= 1) {
        if (t < o) s[t] += s[t + o];
        __syncthreads();
    }
    if (t == 0) g_bsum[b] = s[0];
}

__global__ void k_scan_top() {
    __shared__ unsigned s[256];
    int t = threadIdx.x;
    unsigned v = (t < 196) ? g_bsum[t] : 0u;
    s[t] = v;
    __syncthreads();
    for (int o = 1; o < 256; o <<= 1) {
        unsigned u = (t >= o) ? s[t - o] : 0u;
        __syncthreads();
        s[t] += u;
        __syncthreads();
    }
    g_btop[t] = s[t] - v;
}

__global__ void k_scan_out() {
    __shared__ unsigned s[256];
    int b = blockIdx.x, t = threadIdx.x, i = b * 256 + t;
    unsigned c = (i < V_PAD) ? g_count[i] : 0u;
    s[t] = c;
    __syncthreads();
    for (int o = 1; o < 256; o <<= 1) {
        unsigned u = (t >= o) ? s[t - o] : 0u;
        __syncthreads();
        s[t] += u;
        __syncthreads();
    }
    if (i < V_PAD) g_offset[i] = g_btop[b] + s[t] - c;
}

__global__ void k_scatter(const int* __restrict__ vid) {
    int e = blockIdx.x * 256 + threadIdx.x;
    int v = __ldg(&vid[e]);
    unsigned p = atomicAdd(&g_offset[v], 1u);
    g_order[p] = e;
    g_svid[p] = v;
}

// ---------------- prep ----------------
__global__ void k_prep_w(const float* __restrict__ W1,
                         const float* __restrict__ W2e,
                         const float* __restrict__ W2v) {
    int i = blockIdx.x * 256 + threadIdx.x;
    if (i < C_MID * C_IN) {
        int n = i >> 7, k = i & 127;
        float w = W1[i];
        __nv_bfloat16 hi = __float2bfloat16(w);
        __nv_bfloat16 lo = __float2bfloat16(w - __bfloat162float(hi));
        g_B1[n * KTOT + k] = hi;
        g_B1[n * KTOT + 128 + k] = hi;
        g_B1[n * KTOT + 256 + k] = lo;
    }
    if (i < C_OUT * C_IN) {
        int n = i >> 7, k = i & 127;
        float w = W2e[i];
        __nv_bfloat16 hi = __float2bfloat16(w);
        __nv_bfloat16 lo = __float2bfloat16(w - __bfloat162float(hi));
        g_B3[n * KTOT + k] = hi;
        g_B3[n * KTOT + 128 + k] = hi;
        g_B3[n * KTOT + 256 + k] = lo;
    }
    if (i < C_OUT * C_MID) {   // W2v (128,256) -> g_B2v [128][768]
        int n = i >> 8, k = i & 255;
        float w = W2v[i];
        __nv_bfloat16 hi = __float2bfloat16(w);
        __nv_bfloat16 lo = __float2bfloat16(w - __bfloat162float(hi));
        g_B2v[n * 768 + k] = hi;
        g_B2v[n * 768 + 256 + k] = hi;
        g_B2v[n * 768 + 512 + k] = lo;
    }
}

// gather-split: sorted row p <- original edge order[p]
__global__ void k_split_x(const float* __restrict__ x) {
    size_t i = (size_t)blockIdx.x * 256 + threadIdx.x;   // unit = 4 floats
    int prow = (int)(i >> 5);
    int q = (int)(i & 31);
    int e = __ldg(&g_order[prow]);
    float4 v = __ldg(reinterpret_cast<const float4*>(x + (size_t)e * C_IN) + q);
    ushort4 h, l;
    __nv_bfloat16 hb, lb;
    hb = __float2bfloat16(v.x); lb = __float2bfloat16(v.x - __bfloat162float(hb));
    h.x = *(unsigned short*)&hb; l.x = *(unsigned short*)&lb;
    hb = __float2bfloat16(v.y); lb = __float2bfloat16(v.y - __bfloat162float(hb));
    h.y = *(unsigned short*)&hb; l.y = *(unsigned short*)&lb;
    hb = __float2bfloat16(v.z); lb = __float2bfloat16(v.z - __bfloat162float(hb));
    h.z = *(unsigned short*)&hb; l.z = *(unsigned short*)&lb;
    hb = __float2bfloat16(v.w); lb = __float2bfloat16(v.w - __bfloat162float(hb));
    h.w = *(unsigned short*)&hb; l.w = *(unsigned short*)&lb;
    reinterpret_cast<ushort4*>(g_xhi)[i] = h;
    reinterpret_cast<ushort4*>(g_xlo)[i] = l;
}

// fix -inf -> 0, add deferred b1, split z_vmax to bf16 hi/lo
__global__ void k_split_z(const float* __restrict__ b1) {
    size_t i = (size_t)blockIdx.x * 256 + threadIdx.x;   // unit = 4 floats
    if (i >= (size_t)V_PAD * C_MID / 4) return;
    float4 v = reinterpret_cast<const float4*>(g_zvmax)[i];
    float4 bb = __ldg(reinterpret_cast<const float4*>(b1) + (i & 63));
    v.x = (v.x < -1e38f) ? 0.0f : v.x + bb.x;
    v.y = (v.y < -1e38f) ? 0.0f : v.y + bb.y;
    v.z = (v.z < -1e38f) ? 0.0f : v.z + bb.z;
    v.w = (v.w < -1e38f) ? 0.0f : v.w + bb.w;
    ushort4 h, l;
    __nv_bfloat16 hb, lb;
    hb = __float2bfloat16(v.x); lb = __float2bfloat16(v.x - __bfloat162float(hb));
    h.x = *(unsigned short*)&hb; l.x = *(unsigned short*)&lb;
    hb = __float2bfloat16(v.y); lb = __float2bfloat16(v.y - __bfloat162float(hb));
    h.y = *(unsigned short*)&hb; l.y = *(unsigned short*)&lb;
    hb = __float2bfloat16(v.z); lb = __float2bfloat16(v.z - __bfloat162float(hb));
    h.z = *(unsigned short*)&hb; l.z = *(unsigned short*)&lb;
    hb = __float2bfloat16(v.w); lb = __float2bfloat16(v.w - __bfloat162float(hb));
    h.w = *(unsigned short*)&hb; l.w = *(unsigned short*)&lb;
    reinterpret_cast<uint2*>(g_zhi)[i] = make_uint2((unsigned)h.x | ((unsigned)h.y << 16),
                                                    (unsigned)h.z | ((unsigned)h.w << 16));
    reinterpret_cast<uint2*>(g_zlo)[i] = make_uint2((unsigned)l.x | ((unsigned)l.y << 16),
                                                    (unsigned)l.z | ((unsigned)l.w << 16));
}

__global__ void k_init_zvmax() {
    int i = blockIdx.x * blockDim.x + threadIdx.x;
    const float NEG_INF = __int_as_float(0xFF800000);
    if (i < (V_PAD * C_MID) / 4)
        reinterpret_cast<float4*>(g_zvmax)[i] = make_float4(NEG_INF, NEG_INF, NEG_INF, NEG_INF);
}

// ---------------- GEMM1: z = xs@W1^T, in-tile run-max, few atomics ----------------
__global__ void __launch_bounds__(256, 2)
k_mma1() {
    extern __shared__ char smem[];
    uint32_t sbase = smem_to_u32(smem);
    __shared__ int s_vid[128];
    const int tid = threadIdx.x, wid = tid >> 5, lane = tid & 31;
    const int warp_m = wid & 3, warp_n = wid >> 2;
    const int arow0 = blockIdx.y * 128, bcol0 = blockIdx.x * 128;

    float acc[2][8][4] = {};
    mma_mainloop(g_B1, arow0, bcol0, sbase, acc, tid, lane, warp_m, warp_n);

    // dump fragments to smem [128 rows][stride 132]
    float* s_acc = reinterpret_cast<float*>(smem);
    const int lr4 = lane >> 2, lc2 = (lane & 3) * 2;
#pragma unroll
    for (int mi = 0; mi < 2; mi++) {
        int r0 = warp_m * 32 + mi * 16 + lr4;
#pragma unroll
        for (int nj = 0; nj < 8; nj++) {
            int col = warp_n * 64 + nj * 8 + lc2;
            s_acc[r0 * 132 + col]           = acc[mi][nj][0];
            s_acc[r0 * 132 + col + 1]       = acc[mi][nj][1];
            s_acc[(r0 + 8) * 132 + col]     = acc[mi][nj][2];
            s_acc[(r0 + 8) * 132 + col + 1] = acc[mi][nj][3];
        }
    }
    if (tid < 128) s_vid[tid] = __ldg(&g_svid[arow0 + tid]);
    __syncthreads();

    // per-column run-max over sorted rows: ~1 atomic per (vertex run, col)
    const int col = tid & 127;
    const int rbeg = (tid >> 7) * 64;
    int vcur = s_vid[rbeg];
    float cur = s_acc[rbeg * 132 + col];
    for (int r = rbeg + 1; r < rbeg + 64; r++) {
        int v = s_vid[r];
        float val = s_acc[r * 132 + col];
        if (v != vcur) {
            atomicMaxFloat(&g_zvmax[(size_t)vcur * C_MID + bcol0 + col], cur);
            vcur = v;
            cur = val;
        } else {
            cur = fmaxf(cur, val);
        }
    }
    atomicMaxFloat(&g_zvmax[(size_t)vcur * C_MID + bcol0 + col], cur);
}

// ---------------- GEMM2 (HMMA): z_vertex = split(z_vmax+b1) @ W2v^T ----------------
__global__ void __launch_bounds__(256, 2)
k_mma2() {
    extern __shared__ char smem[];
    uint32_t sbase = smem_to_u32(smem);
    const int tid = threadIdx.x, wid = tid >> 5, lane = tid & 31;
    const int warp_m = wid & 3, warp_n = wid >> 2;
    const int arow0 = blockIdx.x * 128;

    const uint32_t sA[2] = {sbase, sbase + 16384};
    const uint32_t sB[2] = {sbase + 32768, sbase + 49152};
    const char* zh = (const char*)g_zhi + (size_t)arow0 * 512;
    const char* zl = (const char*)g_zlo + (size_t)arow0 * 512;
    const char* bb = (const char*)g_B2v;

    float acc[2][8][4] = {};
    // chunk c: A = (c<4 || c>=8 ? hi : lo) + (c&3)*128 bytes, row stride 512
    load_tile(sA[0], zh, 512, tid);
    load_tile(sB[0], bb, 1536, tid);
    CP_COMMIT();
#pragma unroll
    for (int c = 0; c < NCHUNK2; c++) {
        if (c < NCHUNK2 - 1) {
            int n = c + 1;
            const char* ab = ((n < 4 || n >= 8) ? zh : zl) + (n & 3) * 128;
            load_tile(sA[n & 1], ab, 512, tid);
            load_tile(sB[n & 1], bb + n * 128, 1536, tid);
            CP_COMMIT();
            CP_WAIT1();
        } else {
            CP_WAIT0();
        }
        __syncthreads();
        compute_stage(sA[c & 1], sB[c & 1], acc, lane, warp_m, warp_n);
        __syncthreads();
    }

    const int lr4 = lane >> 2, lc2 = (lane & 3) * 2;
#pragma unroll
    for (int mi = 0; mi < 2; mi++) {
        int p0 = arow0 + warp_m * 32 + mi * 16 + lr4;
        int p1 = p0 + 8;
#pragma unroll
        for (int nj = 0; nj < 8; nj++) {
            int col = warp_n * 64 + nj * 8 + lc2;
            if (p0 < V_SEG)
                *reinterpret_cast<float2*>(&g_zvertex[(size_t)p0 * C_OUT + col]) =
                    make_float2(acc[mi][nj][0], acc[mi][nj][1]);
            if (p1 < V_SEG)
                *reinterpret_cast<float2*>(&g_zvertex[(size_t)p1 * C_OUT + col]) =
                    make_float2(acc[mi][nj][2], acc[mi][nj][3]);
        }
    }
}

// ---------------- GEMM3: out[order[p]] = xs@W2e^T + z_vertex[svid[p]] ----------------
__global__ void __launch_bounds__(256, 2)
k_mma3(float* __restrict__ out) {
    extern __shared__ char smem[];
    uint32_t sbase = smem_to_u32(smem);
    const int tid = threadIdx.x, wid = tid >> 5, lane = tid & 31;
    const int warp_m = wid & 3, warp_n = wid >> 2;
    const int arow0 = blockIdx.x * 128;

    float acc[2][8][4] = {};
    mma_mainloop(g_B3, arow0, 0, sbase, acc, tid, lane, warp_m, warp_n);

    const int lr4 = lane >> 2, lc2 = (lane & 3) * 2;
#pragma unroll
    for (int mi = 0; mi < 2; mi++) {
        int p0 = arow0 + warp_m * 32 + mi * 16 + lr4;
        int p1 = p0 + 8;
        int v0 = __ldg(&g_svid[p0]);
        int v1 = __ldg(&g_svid[p1]);
        int e0 = __ldg(&g_order[p0]);
        int e1 = __ldg(&g_order[p1]);
        const float* z0 = g_zvertex + (size_t)v0 * C_OUT + warp_n * 64 + lc2;
        const float* z1 = g_zvertex + (size_t)v1 * C_OUT + warp_n * 64 + lc2;
        float* o0 = out + (size_t)e0 * C_OUT + warp_n * 64 + lc2;
        float* o1 = out + (size_t)e1 * C_OUT + warp_n * 64 + lc2;
#pragma unroll
        for (int nj = 0; nj < 8; nj++) {
            float2 za = __ldg(reinterpret_cast<const float2*>(z0 + nj * 8));
            float2 zb = __ldg(reinterpret_cast<const float2*>(z1 + nj * 8));
            *reinterpret_cast<float2*>(o0 + nj * 8) =
                make_float2(acc[mi][nj][0] + za.x, acc[mi][nj][1] + za.y);
            *reinterpret_cast<float2*>(o1 + nj * 8) =
                make_float2(acc[mi][nj][2] + zb.x, acc[mi][nj][3] + zb.y);
        }
    }
}

// ---------------- launch ----------------
static constexpr int SMEM_MMA  = 65536 + 3 * 16384;   // 112 KB: A 64KB + B 3x16KB
static constexpr int SMEM_MMA2 = 65536;               // 64 KB: A 2x16 + B 2x16

extern "C" void kernel_launch(void* const* d_in, const int* in_sizes, int n_in,
                              void* d_out, int out_size) {
    const float* x   = (const float*)d_in[0];
    const int*   vid = (const int*)d_in[1];
    const float* W1  = (const float*)d_in[2];
    const float* b1  = (const float*)d_in[3];
    const float* W2e = (const float*)d_in[4];
    const float* W2v = (const float*)d_in[5];
    float* out = (float*)d_out;

    cudaFuncSetAttribute(k_mma1, cudaFuncAttributeMaxDynamicSharedMemorySize, SMEM_MMA);
    cudaFuncSetAttribute(k_mma2, cudaFuncAttributeMaxDynamicSharedMemorySize, SMEM_MMA2);
    cudaFuncSetAttribute(k_mma3, cudaFuncAttributeMaxDynamicSharedMemorySize, SMEM_MMA);

    k_prep_w<<<128, 256>>>(W1, W2e, W2v);
    k_zero_count<<<(V_PAD + 255) / 256, 256>>>();
    k_hist<<<E_EDGES / 256, 256>>>(vid);
    k_scan_part<<<196, 256>>>();
    k_scan_top<<<1, 256>>>();
    k_scan_out<<<196, 256>>>();
    k_scatter<<<E_EDGES / 256, 256>>>(vid);
    k_split_x<<<(E_EDGES * C_IN / 4) / 256, 256>>>(x);
    k_init_zvmax<<<(V_PAD * C_MID / 4 + 255) / 256, 256>>>();
    k_mma1<<<dim3(2, E_EDGES / 128), 256, SMEM_MMA>>>();
    k_split_z<<<(V_PAD * C_MID / 4 + 255) / 256, 256>>>(b1);
    k_mma2<<<V_PAD / 128, 256, SMEM_MMA2>>>();
    k_mma3<<<E_EDGES / 128, 256, SMEM_MMA>>>(out);
}